// round 16
// baseline (speedup 1.0000x reference)
#include <cuda_runtime.h>
#include <math.h>

// ---------------------------------------------------------------------------
// YOLOX loss, B=64, A=8400, M=50, 80 classes.
// R16 = R15 + per-block GT y-band pruning before argmin:
//   - block anchors span a narrow y-range; GTs with cy outside
//     [ay_min-64, ay_max+64] can never yield d2<4096 in this block, so they
//     cannot affect pos or the matched index (argmin winner for positives is
//     always inside the band; order-preserving compaction keeps tie-break)
//   - argmin V drops ~30 -> ~7 on the 25 stride-8 blocks
//   - everything else identical to R15 (pooled positive queue, depth-1
//     load-only prefetch, grouped-log softplus, packed-key argmin)
// ---------------------------------------------------------------------------

#define NUM_A     8400
#define NUM_M     50
#define BLK       256
#define WARPS     (BLK / 32)
#define BLKS_IMG  33          // 33*256 = 8448 threads >= 8400 anchors
#define NBLOCKS   (BLKS_IMG * 64)
#define FULLMASK  0xffffffffu
#define L2E       1.4426950408889634f
#define LN2       0.6931471805599453f
#define SENT      -200.0f     // exp2f(SENT*L2E) == 0 exactly -> factor 1.0

// per (img, block): obj_sum, cls_raw, box_raw, num_pos
__device__ float    g_part[64 * BLKS_IMG * 4];
__device__ unsigned g_ticket = 0;

__device__ __forceinline__ float spl2(float x) {   // softplus(x)/ln2
    return __log2f(1.0f + exp2f(x * L2E));
}
__device__ __forceinline__ float spfac(float x) {  // 1 + e^x
    return 1.0f + exp2f(x * L2E);
}

__global__ __launch_bounds__(BLK) void yolox_main_kernel(
    const float* __restrict__ pred,    // (64, 8400, 85)
    const float* __restrict__ tgt,     // (64, 50, 5)
    float* __restrict__ out)           // [5]
{
    __shared__ float2 s_ctr[NUM_M];    // compacted (then pruned) GT centers
    __shared__ float  s_x1[NUM_M], s_y1[NUM_M], s_x2[NUM_M], s_y2[NUM_M];
    __shared__ float  s_ta[NUM_M];
    __shared__ int    s_cls[NUM_M];
    __shared__ int    s_w0cnt, s_V;
    __shared__ float  s_red[WARPS][4];
    __shared__ int    s_last;
    __shared__ int            s_wcnt[WARPS];
    __shared__ unsigned char  s_list[BLK];
    __shared__ float  s_mn[WARPS], s_mx[WARPS];
    __shared__ int    s_keep0, s_vp;

    const int img  = blockIdx.y;
    const int tid  = threadIdx.x;
    const int lane = tid & 31;
    const int warp = tid >> 5;

    // ---- load targets + ballot-prefix compaction of valid GTs ----
    float cx = 0, cy = 0, x1 = 0, y1 = 0, x2 = 0, y2 = 0, ta = 0;
    int   cls = 0, pfx = 0;
    bool  ok = false;
    if (tid < NUM_M) {
        const unsigned amask = (tid < 32) ? FULLMASK : 0x3ffffu;
        const float* tr = tgt + ((size_t)img * NUM_M + tid) * 5;
        float c = tr[0];
        ok  = (c >= 0.0f);
        cls = (int)c;
        cx = tr[1] * 640.0f; cy = tr[2] * 640.0f;
        float w = tr[3] * 640.0f, h = tr[4] * 640.0f;
        x1 = cx - w * 0.5f; y1 = cy - h * 0.5f;
        x2 = cx + w * 0.5f; y2 = cy + h * 0.5f;
        ta = (x2 - x1) * (y2 - y1);

        unsigned ball = __ballot_sync(amask, ok);
        pfx = __popc(ball & ((1u << lane) - 1u));
        if (tid == 0)  s_w0cnt = __popc(ball);
        if (tid == 32) s_V = __popc(ball);
    }
    __syncthreads();
    if (tid < NUM_M && ok) {
        int slot = pfx + ((tid < 32) ? 0 : s_w0cnt);
        s_ctr[slot] = make_float2(cx, cy);
        s_x1[slot] = x1; s_y1[slot] = y1;
        s_x2[slot] = x2; s_y2[slot] = y2;
        s_ta[slot] = ta; s_cls[slot] = cls;
    }
    if (tid == 0) s_V += s_w0cnt;
    __syncthreads();

    const int    V     = s_V;
    const int    a     = blockIdx.x * BLK + tid;
    const bool   valid = (a < NUM_A);
    const float* base  = pred + (size_t)img * NUM_A * 85;
    const float* myrow = base + (size_t)a * 85;

    // ---- early load: obj logit ----
    float pobj = 0.0f;
    if (valid) pobj = __ldg(myrow + 4);

    // ---- anchor decode (magic multiply) ----
    float ax = 0.0f, ay = 0.0f;
    if (valid) {
        if (a < 6400) {
            int r = (int)(((unsigned)a * 52429u) >> 22);       // a/80
            int c = a - r * 80;
            ax = fmaf((float)c, 8.0f, 4.0f);
            ay = fmaf((float)r, 8.0f, 4.0f);
        } else if (a < 8000) {
            int i = a - 6400;
            int r = (int)(((unsigned)i * 52429u) >> 21);       // i/40
            int c = i - r * 40;
            ax = fmaf((float)c, 16.0f, 8.0f);
            ay = fmaf((float)r, 16.0f, 8.0f);
        } else {
            int i = a - 8000;
            int r = (int)(((unsigned)i * 52429u) >> 20);       // i/20
            int c = i - r * 20;
            ax = fmaf((float)c, 32.0f, 16.0f);
            ay = fmaf((float)r, 32.0f, 16.0f);
        }
    }

    // ---- block ay min/max (for GT y-band prune) ----
    float amn = valid ? ay : 1e30f;
    float amx = valid ? ay : -1e30f;
    #pragma unroll
    for (int o = 16; o; o >>= 1) {
        amn = fminf(amn, __shfl_down_sync(FULLMASK, amn, o));
        amx = fmaxf(amx, __shfl_down_sync(FULLMASK, amx, o));
    }
    if (lane == 0) { s_mn[warp] = amn; s_mx[warp] = amx; }
    __syncthreads();
    float bmn = 1e30f, bmx = -1e30f;
    #pragma unroll
    for (int i = 0; i < WARPS; i++) {
        bmn = fminf(bmn, s_mn[i]);
        bmx = fmaxf(bmx, s_mx[i]);
    }
    bmn -= 64.0f; bmx += 64.0f;

    // ---- prune GTs to the y-band (order-preserving in-place compaction) ----
    float2 pc = make_float2(0, 0);
    float  px1 = 0, py1 = 0, px2 = 0, py2 = 0, pta = 0;
    int    pcls = 0, kslot = 0;
    bool   keep = false;
    if (tid < 64) {
        if (tid < V) {
            pc  = s_ctr[tid];
            px1 = s_x1[tid]; py1 = s_y1[tid];
            px2 = s_x2[tid]; py2 = s_y2[tid];
            pta = s_ta[tid]; pcls = s_cls[tid];
            keep = (pc.y >= bmn) && (pc.y <= bmx);
        }
        unsigned kb = __ballot_sync(FULLMASK, keep);
        kslot = __popc(kb & ((1u << lane) - 1u));
        if (tid == 0)  s_keep0 = __popc(kb);
        if (tid == 32) s_vp = __popc(kb);
    }
    __syncthreads();
    if (keep) {
        int slot = kslot + ((tid < 32) ? 0 : s_keep0);
        s_ctr[slot] = pc;
        s_x1[slot] = px1; s_y1[slot] = py1;
        s_x2[slot] = px2; s_y2[slot] = py2;
        s_ta[slot] = pta; s_cls[slot] = pcls;
    }
    if (tid == 0) s_vp += s_keep0;
    __syncthreads();
    const int Vp = s_vp;

    // ---- packed-key argmin over pruned GTs ----
    int k0 = 0x7f800000, k1 = 0x7f800000;   // +INF, idx 0
    int m = 0;
    for (; m + 1 < Vp; m += 2) {
        float2 c0 = s_ctr[m];
        float2 c1 = s_ctr[m + 1];
        float dx0 = c0.x - ax, dy0 = c0.y - ay;
        float dx1 = c1.x - ax, dy1 = c1.y - ay;
        float d20 = fmaf(dx0, dx0, dy0 * dy0);
        float d21 = fmaf(dx1, dx1, dy1 * dy1);
        k0 = min(k0, (__float_as_int(d20) & ~63) | m);
        k1 = min(k1, (__float_as_int(d21) & ~63) | (m + 1));
    }
    if (m < Vp) {
        float2 c0 = s_ctr[m];
        float dx0 = c0.x - ax, dy0 = c0.y - ay;
        float d20 = fmaf(dx0, dx0, dy0 * dy0);
        k0 = min(k0, (__float_as_int(d20) & ~63) | m);
    }
    int   kbest = min(k0, k1);
    int   bidx  = kbest & 63;
    float best  = __int_as_float(kbest & ~63);

    const bool  pos  = valid && (best < 4096.0f);   // DIST_THRESH_SQ
    const float posf = pos ? 1.0f : 0.0f;

    float w_obj = 0.0f;
    if (valid) w_obj = fmaf(spl2(pobj), LN2, -posf * pobj);   // bce(pobj, posf)

    // ---- build block-pooled positive-row list ----
    unsigned pmw = __ballot_sync(FULLMASK, pos);
    if (lane == 0) s_wcnt[warp] = __popc(pmw);
    __syncthreads();

    int off = 0, total = 0;
    #pragma unroll
    for (int i = 0; i < WARPS; i++) {
        int c = s_wcnt[i];
        if (i < warp) off += c;
        total += c;
    }
    if (pos) {
        int ppfx = __popc(pmw & ((1u << lane) - 1u));
        s_list[off + ppfx] = (unsigned char)tid;
    }
    __syncthreads();

    // ---- phase 2: pooled grouped-log softplus, depth-1 load pipeline ----
    const int ablk = blockIdx.x * BLK;
    float w_cls_l2 = 0.0f;                          // log2 units

    int ka = warp, kb = warp + WARPS;
    float A0 = SENT, A1 = SENT, A2 = SENT;
    float B0 = SENT, B1 = SENT, B2 = SENT;
    if (ka < total) {
        const float* ra = base + (size_t)(ablk + s_list[ka]) * 85;
        A0 = __ldg(ra + 5  + lane);
        A1 = __ldg(ra + 37 + lane);
        A2 = (lane < 16) ? __ldg(ra + 69 + lane) : SENT;
        if (kb < total) {
            const float* rb = base + (size_t)(ablk + s_list[kb]) * 85;
            B0 = __ldg(rb + 5  + lane);
            B1 = __ldg(rb + 37 + lane);
            B2 = (lane < 16) ? __ldg(rb + 69 + lane) : SENT;
        }
    }
    while (ka < total) {
        int na = ka + 2 * WARPS, nb = kb + 2 * WARPS;
        float C0 = SENT, C1 = SENT, C2 = SENT;
        float D0 = SENT, D1 = SENT, D2 = SENT;
        if (na < total) {
            const float* ra = base + (size_t)(ablk + s_list[na]) * 85;
            C0 = __ldg(ra + 5  + lane);
            C1 = __ldg(ra + 37 + lane);
            C2 = (lane < 16) ? __ldg(ra + 69 + lane) : SENT;
            if (nb < total) {
                const float* rb = base + (size_t)(ablk + s_list[nb]) * 85;
                D0 = __ldg(rb + 5  + lane);
                D1 = __ldg(rb + 37 + lane);
                D2 = (lane < 16) ? __ldg(rb + 69 + lane) : SENT;
            }
        }

        float P = spfac(A0) * spfac(A1) * spfac(A2)
                * spfac(B0) * spfac(B1) * spfac(B2);
        w_cls_l2 += __log2f(P);

        ka = na; kb = nb;
        A0 = C0; A1 = C1; A2 = C2;
        B0 = D0; B1 = D1; B2 = D2;
    }
    float w_cls = w_cls_l2 * LN2;

    // ---- phase 2b + 3: matched subtract + IoU (own anchor; L1/L2 hits) ----
    float w_box = 0.0f, w_pos = 0.0f;
    if (pos) {
        w_cls -= __ldg(myrow + 5 + s_cls[bidx]);

        float r0 = __ldg(myrow + 0);
        float r1 = __ldg(myrow + 1);
        float r2 = __ldg(myrow + 2);
        float r3 = __ldg(myrow + 3);
        float ew = __expf(r2), eh = __expf(r3);
        float p1x = r0 - ew * 0.5f, p2x = r0 + ew * 0.5f;
        float p1y = r1 - eh * 0.5f, p2y = r1 + eh * 0.5f;
        float ix = fminf(p2x, s_x2[bidx]) - fmaxf(p1x, s_x1[bidx]);
        float iy = fminf(p2y, s_y2[bidx]) - fmaxf(p1y, s_y1[bidx]);
        float inter = fmaxf(ix, 0.0f) * fmaxf(iy, 0.0f);
        float pa    = (p2x - p1x) * (p2y - p1y);
        float uni   = pa + s_ta[bidx] - inter;
        w_box = 1.0f - inter / (uni + 1e-6f);
        w_pos = 1.0f;
    }

    // ---- reduction: warp -> block -> g_part ----
    #pragma unroll
    for (int o = 16; o; o >>= 1) {
        w_obj += __shfl_down_sync(FULLMASK, w_obj, o);
        w_cls += __shfl_down_sync(FULLMASK, w_cls, o);
        w_box += __shfl_down_sync(FULLMASK, w_box, o);
        w_pos += __shfl_down_sync(FULLMASK, w_pos, o);
    }
    if (lane == 0) {
        s_red[warp][0] = w_obj;
        s_red[warp][1] = w_cls;
        s_red[warp][2] = w_box;
        s_red[warp][3] = w_pos;
    }
    __syncthreads();

    if (tid == 0) {
        float o = 0.0f, c = 0.0f, b = 0.0f, p = 0.0f;
        #pragma unroll
        for (int i = 0; i < WARPS; i++) {
            o += s_red[i][0]; c += s_red[i][1];
            b += s_red[i][2]; p += s_red[i][3];
        }
        float* dst = g_part + ((size_t)img * BLKS_IMG + blockIdx.x) * 4;
        dst[0] = o; dst[1] = c; dst[2] = b; dst[3] = p;
        __threadfence();
        unsigned t = atomicAdd(&g_ticket, 1u);
        s_last = (t == NBLOCKS - 1) ? 1 : 0;
    }
    __syncthreads();

    // ---- last block: final reduction (deterministic values) ----
    if (s_last) {
        __shared__ float sw[8][4];
        __shared__ float sfin[4];
        const int rimg = tid >> 2;         // 0..63
        const int comp = tid & 3;          // 0=obj,1=cls,2=box,3=np

        float s = 0.0f;
        const float* p = g_part + (size_t)rimg * BLKS_IMG * 4 + comp;
        #pragma unroll
        for (int b = 0; b < BLKS_IMG; b++) s += p[b * 4];

        float np  = __shfl_sync(FULLMASK, s, lane | 3);
        float den = fmaxf(np, 1.0f);

        float v;
        if (comp == 0)      v = s / 8400.0f;
        else if (comp == 1) v = (np > 0.0f) ? s / (den * 80.0f) : 0.0f;
        else if (comp == 2) v = (np > 0.0f) ? s / den : 0.0f;
        else                v = s;

        #pragma unroll
        for (int o = 4; o < 32; o <<= 1)
            v += __shfl_down_sync(FULLMASK, v, o);

        if (lane < 4) sw[warp][lane] = v;
        __syncthreads();

        if (tid < 4) {
            float t = 0.0f;
            #pragma unroll
            for (int w = 0; w < 8; w++) t += sw[w][tid];
            sfin[tid] = t;
        }
        __syncthreads();

        if (tid == 0) {
            float obj = sfin[0], cls = sfin[1], box = sfin[2], np = sfin[3];
            out[0] = 5.0f * box + obj + cls;
            out[1] = box;
            out[2] = obj;
            out[3] = cls;
            out[4] = np;
            g_ticket = 0;      // reset for next graph replay
        }
    }
}

extern "C" void kernel_launch(void* const* d_in, const int* in_sizes, int n_in,
                              void* d_out, int out_size) {
    const float* pred = (const float*)d_in[0];
    const float* tgt  = (const float*)d_in[1];
    float* out = (float*)d_out;

    dim3 grid(BLKS_IMG, 64);
    yolox_main_kernel<<<grid, BLK>>>(pred, tgt, out);
}

// round 17
// speedup vs baseline: 1.0460x; 1.0460x over previous
#include <cuda_runtime.h>
#include <math.h>

// ---------------------------------------------------------------------------
// YOLOX loss, B=64, A=8400, M=50, 80 classes.
// R17 = R15 + y-band GT prune done the cheap way:
//   - prune runs serially in warp 0 (2 chunks of 32), writes to SEPARATE
//     dst SMEM arrays -> no per-thread state across barriers, main-path
//     registers untouched (R16's regs 31->40 / occ 82->65 regression fixed)
//   - __launch_bounds__(BLK, 8) pins 32 regs / 8 blocks per SM
//   - else identical to R15 (pooled positive queue, depth-1 load-only
//     prefetch, grouped-log softplus, packed-key argmin)
// ---------------------------------------------------------------------------

#define NUM_A     8400
#define NUM_M     50
#define BLK       256
#define WARPS     (BLK / 32)
#define BLKS_IMG  33          // 33*256 = 8448 threads >= 8400 anchors
#define NBLOCKS   (BLKS_IMG * 64)
#define FULLMASK  0xffffffffu
#define L2E       1.4426950408889634f
#define LN2       0.6931471805599453f
#define SENT      -200.0f     // exp2f(SENT*L2E) == 0 exactly -> factor 1.0

// per (img, block): obj_sum, cls_raw, box_raw, num_pos
__device__ float    g_part[64 * BLKS_IMG * 4];
__device__ unsigned g_ticket = 0;

__device__ __forceinline__ float spl2(float x) {   // softplus(x)/ln2
    return __log2f(1.0f + exp2f(x * L2E));
}
__device__ __forceinline__ float spfac(float x) {  // 1 + e^x
    return 1.0f + exp2f(x * L2E);
}

__global__ __launch_bounds__(BLK, 8) void yolox_main_kernel(
    const float* __restrict__ pred,    // (64, 8400, 85)
    const float* __restrict__ tgt,     // (64, 50, 5)
    float* __restrict__ out)           // [5]
{
    __shared__ float2 s_ctr[NUM_M];    // compacted valid GT centers (src)
    __shared__ float  s_x1[NUM_M], s_y1[NUM_M], s_x2[NUM_M], s_y2[NUM_M];
    __shared__ float  s_ta[NUM_M];
    __shared__ int    s_cls[NUM_M];
    __shared__ float2 p_ctr[NUM_M];    // y-band pruned GTs (dst)
    __shared__ float  p_x1[NUM_M], p_y1[NUM_M], p_x2[NUM_M], p_y2[NUM_M];
    __shared__ float  p_ta[NUM_M];
    __shared__ int    p_cls[NUM_M];
    __shared__ int    s_w0cnt, s_V, s_vp;
    __shared__ float  s_red[WARPS][4];
    __shared__ int    s_last;
    __shared__ int            s_wcnt[WARPS];
    __shared__ unsigned char  s_list[BLK];
    __shared__ float  s_mn[WARPS], s_mx[WARPS];

    const int img  = blockIdx.y;
    const int tid  = threadIdx.x;
    const int lane = tid & 31;
    const int warp = tid >> 5;

    // ---- load targets + ballot-prefix compaction of valid GTs ----
    float cx = 0, cy = 0, x1 = 0, y1 = 0, x2 = 0, y2 = 0, ta = 0;
    int   cls = 0, pfx = 0;
    bool  ok = false;
    if (tid < NUM_M) {
        const unsigned amask = (tid < 32) ? FULLMASK : 0x3ffffu;
        const float* tr = tgt + ((size_t)img * NUM_M + tid) * 5;
        float c = tr[0];
        ok  = (c >= 0.0f);
        cls = (int)c;
        cx = tr[1] * 640.0f; cy = tr[2] * 640.0f;
        float w = tr[3] * 640.0f, h = tr[4] * 640.0f;
        x1 = cx - w * 0.5f; y1 = cy - h * 0.5f;
        x2 = cx + w * 0.5f; y2 = cy + h * 0.5f;
        ta = (x2 - x1) * (y2 - y1);

        unsigned ball = __ballot_sync(amask, ok);
        pfx = __popc(ball & ((1u << lane) - 1u));
        if (tid == 0)  s_w0cnt = __popc(ball);
        if (tid == 32) s_V = __popc(ball);
    }
    __syncthreads();
    if (tid < NUM_M && ok) {
        int slot = pfx + ((tid < 32) ? 0 : s_w0cnt);
        s_ctr[slot] = make_float2(cx, cy);
        s_x1[slot] = x1; s_y1[slot] = y1;
        s_x2[slot] = x2; s_y2[slot] = y2;
        s_ta[slot] = ta; s_cls[slot] = cls;
    }
    if (tid == 0) s_V += s_w0cnt;
    __syncthreads();

    const int    a     = blockIdx.x * BLK + tid;
    const bool   valid = (a < NUM_A);
    const float* base  = pred + (size_t)img * NUM_A * 85;
    const float* myrow = base + (size_t)a * 85;

    // ---- early load: obj logit ----
    float pobj = 0.0f;
    if (valid) pobj = __ldg(myrow + 4);

    // ---- anchor decode (magic multiply) ----
    float ax = 0.0f, ay = 0.0f;
    if (valid) {
        if (a < 6400) {
            int r = (int)(((unsigned)a * 52429u) >> 22);       // a/80
            int c = a - r * 80;
            ax = fmaf((float)c, 8.0f, 4.0f);
            ay = fmaf((float)r, 8.0f, 4.0f);
        } else if (a < 8000) {
            int i = a - 6400;
            int r = (int)(((unsigned)i * 52429u) >> 21);       // i/40
            int c = i - r * 40;
            ax = fmaf((float)c, 16.0f, 8.0f);
            ay = fmaf((float)r, 16.0f, 8.0f);
        } else {
            int i = a - 8000;
            int r = (int)(((unsigned)i * 52429u) >> 20);       // i/20
            int c = i - r * 20;
            ax = fmaf((float)c, 32.0f, 16.0f);
            ay = fmaf((float)r, 32.0f, 16.0f);
        }
    }

    // ---- block ay min/max (cheap reduce; feeds warp-0 prune) ----
    {
        float amn = valid ? ay : 1e30f;
        float amx = valid ? ay : -1e30f;
        #pragma unroll
        for (int o = 16; o; o >>= 1) {
            amn = fminf(amn, __shfl_down_sync(FULLMASK, amn, o));
            amx = fmaxf(amx, __shfl_down_sync(FULLMASK, amx, o));
        }
        if (lane == 0) { s_mn[warp] = amn; s_mx[warp] = amx; }
    }
    __syncthreads();

    // ---- warp-0-serial y-band prune into dst arrays (no carried state) ----
    if (warp == 0) {
        float bmn = 1e30f, bmx = -1e30f;
        #pragma unroll
        for (int i = 0; i < WARPS; i++) {
            bmn = fminf(bmn, s_mn[i]);
            bmx = fmaxf(bmx, s_mx[i]);
        }
        bmn -= 64.0f; bmx += 64.0f;

        const int V = s_V;
        int cnt = 0;
        #pragma unroll
        for (int ch = 0; ch < 2; ch++) {
            int i = ch * 32 + lane;
            bool keep = false;
            float2 c2 = make_float2(0, 0);
            if (i < V) {
                c2 = s_ctr[i];
                keep = (c2.y >= bmn) && (c2.y <= bmx);
            }
            unsigned kb = __ballot_sync(FULLMASK, keep);
            if (keep) {
                int slot = cnt + __popc(kb & ((1u << lane) - 1u));
                p_ctr[slot] = c2;
                p_x1[slot] = s_x1[i]; p_y1[slot] = s_y1[i];
                p_x2[slot] = s_x2[i]; p_y2[slot] = s_y2[i];
                p_ta[slot] = s_ta[i]; p_cls[slot] = s_cls[i];
            }
            cnt += __popc(kb);
        }
        if (lane == 0) s_vp = cnt;
    }
    __syncthreads();
    const int Vp = s_vp;

    // ---- packed-key argmin over pruned GTs ----
    int k0 = 0x7f800000, k1 = 0x7f800000;   // +INF, idx 0
    int m = 0;
    for (; m + 1 < Vp; m += 2) {
        float2 c0 = p_ctr[m];
        float2 c1 = p_ctr[m + 1];
        float dx0 = c0.x - ax, dy0 = c0.y - ay;
        float dx1 = c1.x - ax, dy1 = c1.y - ay;
        float d20 = fmaf(dx0, dx0, dy0 * dy0);
        float d21 = fmaf(dx1, dx1, dy1 * dy1);
        k0 = min(k0, (__float_as_int(d20) & ~63) | m);
        k1 = min(k1, (__float_as_int(d21) & ~63) | (m + 1));
    }
    if (m < Vp) {
        float2 c0 = p_ctr[m];
        float dx0 = c0.x - ax, dy0 = c0.y - ay;
        float d20 = fmaf(dx0, dx0, dy0 * dy0);
        k0 = min(k0, (__float_as_int(d20) & ~63) | m);
    }
    int   kbest = min(k0, k1);
    int   bidx  = kbest & 63;
    float best  = __int_as_float(kbest & ~63);

    const bool  pos  = valid && (best < 4096.0f);   // DIST_THRESH_SQ
    const float posf = pos ? 1.0f : 0.0f;

    float w_obj = 0.0f;
    if (valid) w_obj = fmaf(spl2(pobj), LN2, -posf * pobj);   // bce(pobj, posf)

    // ---- build block-pooled positive-row list ----
    unsigned pmw = __ballot_sync(FULLMASK, pos);
    if (lane == 0) s_wcnt[warp] = __popc(pmw);
    __syncthreads();

    int off = 0, total = 0;
    #pragma unroll
    for (int i = 0; i < WARPS; i++) {
        int c = s_wcnt[i];
        if (i < warp) off += c;
        total += c;
    }
    if (pos) {
        int ppfx = __popc(pmw & ((1u << lane) - 1u));
        s_list[off + ppfx] = (unsigned char)tid;
    }
    __syncthreads();

    // ---- phase 2: pooled grouped-log softplus, depth-1 load pipeline ----
    const int ablk = blockIdx.x * BLK;
    float w_cls_l2 = 0.0f;                          // log2 units

    int ka = warp, kb = warp + WARPS;
    float A0 = SENT, A1 = SENT, A2 = SENT;
    float B0 = SENT, B1 = SENT, B2 = SENT;
    if (ka < total) {
        const float* ra = base + (size_t)(ablk + s_list[ka]) * 85;
        A0 = __ldg(ra + 5  + lane);
        A1 = __ldg(ra + 37 + lane);
        A2 = (lane < 16) ? __ldg(ra + 69 + lane) : SENT;
        if (kb < total) {
            const float* rb = base + (size_t)(ablk + s_list[kb]) * 85;
            B0 = __ldg(rb + 5  + lane);
            B1 = __ldg(rb + 37 + lane);
            B2 = (lane < 16) ? __ldg(rb + 69 + lane) : SENT;
        }
    }
    while (ka < total) {
        int na = ka + 2 * WARPS, nb = kb + 2 * WARPS;
        float C0 = SENT, C1 = SENT, C2 = SENT;
        float D0 = SENT, D1 = SENT, D2 = SENT;
        if (na < total) {
            const float* ra = base + (size_t)(ablk + s_list[na]) * 85;
            C0 = __ldg(ra + 5  + lane);
            C1 = __ldg(ra + 37 + lane);
            C2 = (lane < 16) ? __ldg(ra + 69 + lane) : SENT;
            if (nb < total) {
                const float* rb = base + (size_t)(ablk + s_list[nb]) * 85;
                D0 = __ldg(rb + 5  + lane);
                D1 = __ldg(rb + 37 + lane);
                D2 = (lane < 16) ? __ldg(rb + 69 + lane) : SENT;
            }
        }

        float P = spfac(A0) * spfac(A1) * spfac(A2)
                * spfac(B0) * spfac(B1) * spfac(B2);
        w_cls_l2 += __log2f(P);

        ka = na; kb = nb;
        A0 = C0; A1 = C1; A2 = C2;
        B0 = D0; B1 = D1; B2 = D2;
    }
    float w_cls = w_cls_l2 * LN2;

    // ---- phase 2b + 3: matched subtract + IoU (own anchor; L1/L2 hits) ----
    float w_box = 0.0f, w_pos = 0.0f;
    if (pos) {
        w_cls -= __ldg(myrow + 5 + p_cls[bidx]);

        float r0 = __ldg(myrow + 0);
        float r1 = __ldg(myrow + 1);
        float r2 = __ldg(myrow + 2);
        float r3 = __ldg(myrow + 3);
        float ew = __expf(r2), eh = __expf(r3);
        float p1x = r0 - ew * 0.5f, p2x = r0 + ew * 0.5f;
        float p1y = r1 - eh * 0.5f, p2y = r1 + eh * 0.5f;
        float ix = fminf(p2x, p_x2[bidx]) - fmaxf(p1x, p_x1[bidx]);
        float iy = fminf(p2y, p_y2[bidx]) - fmaxf(p1y, p_y1[bidx]);
        float inter = fmaxf(ix, 0.0f) * fmaxf(iy, 0.0f);
        float pa    = (p2x - p1x) * (p2y - p1y);
        float uni   = pa + p_ta[bidx] - inter;
        w_box = 1.0f - inter / (uni + 1e-6f);
        w_pos = 1.0f;
    }

    // ---- reduction: warp -> block -> g_part ----
    #pragma unroll
    for (int o = 16; o; o >>= 1) {
        w_obj += __shfl_down_sync(FULLMASK, w_obj, o);
        w_cls += __shfl_down_sync(FULLMASK, w_cls, o);
        w_box += __shfl_down_sync(FULLMASK, w_box, o);
        w_pos += __shfl_down_sync(FULLMASK, w_pos, o);
    }
    if (lane == 0) {
        s_red[warp][0] = w_obj;
        s_red[warp][1] = w_cls;
        s_red[warp][2] = w_box;
        s_red[warp][3] = w_pos;
    }
    __syncthreads();

    if (tid == 0) {
        float o = 0.0f, c = 0.0f, b = 0.0f, p = 0.0f;
        #pragma unroll
        for (int i = 0; i < WARPS; i++) {
            o += s_red[i][0]; c += s_red[i][1];
            b += s_red[i][2]; p += s_red[i][3];
        }
        float* dst = g_part + ((size_t)img * BLKS_IMG + blockIdx.x) * 4;
        dst[0] = o; dst[1] = c; dst[2] = b; dst[3] = p;
        __threadfence();
        unsigned t = atomicAdd(&g_ticket, 1u);
        s_last = (t == NBLOCKS - 1) ? 1 : 0;
    }
    __syncthreads();

    // ---- last block: final reduction (deterministic values) ----
    if (s_last) {
        __shared__ float sw[8][4];
        __shared__ float sfin[4];
        const int rimg = tid >> 2;         // 0..63
        const int comp = tid & 3;          // 0=obj,1=cls,2=box,3=np

        float s = 0.0f;
        const float* p = g_part + (size_t)rimg * BLKS_IMG * 4 + comp;
        #pragma unroll
        for (int b = 0; b < BLKS_IMG; b++) s += p[b * 4];

        float np  = __shfl_sync(FULLMASK, s, lane | 3);
        float den = fmaxf(np, 1.0f);

        float v;
        if (comp == 0)      v = s / 8400.0f;
        else if (comp == 1) v = (np > 0.0f) ? s / (den * 80.0f) : 0.0f;
        else if (comp == 2) v = (np > 0.0f) ? s / den : 0.0f;
        else                v = s;

        #pragma unroll
        for (int o = 4; o < 32; o <<= 1)
            v += __shfl_down_sync(FULLMASK, v, o);

        if (lane < 4) sw[warp][lane] = v;
        __syncthreads();

        if (tid < 4) {
            float t = 0.0f;
            #pragma unroll
            for (int w = 0; w < 8; w++) t += sw[w][tid];
            sfin[tid] = t;
        }
        __syncthreads();

        if (tid == 0) {
            float obj = sfin[0], cls = sfin[1], box = sfin[2], np = sfin[3];
            out[0] = 5.0f * box + obj + cls;
            out[1] = box;
            out[2] = obj;
            out[3] = cls;
            out[4] = np;
            g_ticket = 0;      // reset for next graph replay
        }
    }
}

extern "C" void kernel_launch(void* const* d_in, const int* in_sizes, int n_in,
                              void* d_out, int out_size) {
    const float* pred = (const float*)d_in[0];
    const float* tgt  = (const float*)d_in[1];
    float* out = (float*)d_out;

    dim3 grid(BLKS_IMG, 64);
    yolox_main_kernel<<<grid, BLK>>>(pred, tgt, out);
}